// round 13
// baseline (speedup 1.0000x reference)
#include <cuda_runtime.h>
#include <cuda_fp16.h>
#include <stdint.h>
#include <stdlib.h>

// ---------------------------------------------------------------------------
// GCN 2-layer forward, N=100k, E=1.6M, d=64.
// Pipeline (6 launches; agg at index 3 = the ncu-captured slot):
//  0 k_deg        degrees via atomics (cnt arrays zero by module init / reset)
//  1 k_scan_stage decoupled-lookback scan of cnt_in -> row_ptr/cursor;
//                 surplus blocks stage h = x*rsqrt(1+deg_out) as fp16
//  2 k_fill       CSR fill (src only; scale folded into staged h)
//  3 k_agg_gemm_q gather u = rin*(h_self + sum h[src]) (fp32 accum),
//                 y = relu(u@W1+b1), q = rout*(y . W2@Wr)
//                 GEMM smem traffic vectorized: WsT[col][k] + float4 over k
//  4 k_out        out = rin*(q_self + sum_in q) + (b2.Wr + br)
//  5 k_reset      re-zero cnt/desc/ticket for the next replay
// ---------------------------------------------------------------------------

#define MAXN 100352
#define MAXE 1605632
#define D 64
#define WPAD 68                      // 68 words: conflict-free LDS.128 phases
#define FULL 0xffffffffu
#define SCAN_TILE 1024
#define MAX_TILES ((MAXN + SCAN_TILE - 1) / SCAN_TILE)

__device__ int   g_cnt_out[MAXN];
__device__ int   g_cnt_in[MAXN];
__device__ int   g_row_ptr[MAXN + 1];
__device__ int   g_cursor[MAXN];
__device__ int   g_csr[MAXE];              // src only (4 B/edge)
__device__ __half2 g_h[MAXN * D / 2];      // staged h = x*rout, fp16 (12.8 MB)
__device__ float g_q[MAXN];
__device__ unsigned long long g_desc[MAX_TILES];  // lookback: status<<32 | value
__device__ unsigned g_scan_ticket;

__attribute__((constructor))
static void _eager_modules() { setenv("CUDA_MODULE_LOADING", "EAGER", 1); }

__device__ __forceinline__ int clampi(int v, int n) { return min(max(v, 0), n - 1); }

// ------------------------------- degrees -----------------------------------

__global__ void k_deg(const int* __restrict__ src, const int* __restrict__ dst,
                      int e, int n) {
    int t = blockIdx.x * blockDim.x + threadIdx.x;
    if (t >= e) return;
    atomicAdd(&g_cnt_out[clampi(src[t], n)], 1);
    atomicAdd(&g_cnt_in[clampi(dst[t], n)], 1);
}

// -------------- single-pass scan (decoupled lookback) + fp16 staging --------

__global__ void k_scan_stage(const float* __restrict__ x, int n, int ntiles) {
    if ((int)blockIdx.x >= ntiles) {
        int idx = (blockIdx.x - ntiles) * 256 + threadIdx.x;   // float4 index
        if (idx < n * (D / 4)) {
            int row = idx >> 4;
            float rt = rsqrtf(1.0f + (float)g_cnt_out[row]);
            float4 v = ((const float4*)x)[idx];
            ((__half2*)g_h)[idx * 2]     = __floats2half2_rn(v.x * rt, v.y * rt);
            ((__half2*)g_h)[idx * 2 + 1] = __floats2half2_rn(v.z * rt, v.w * rt);
        }
        return;
    }

    __shared__ int sh_tile, sh_prefix;
    __shared__ int warp_agg[8];
    const int t = threadIdx.x, lane = t & 31, wy = t >> 5;

    if (t == 0) sh_tile = (int)atomicAdd(&g_scan_ticket, 1u);
    __syncthreads();
    const int tile = sh_tile;
    const int base = tile * SCAN_TILE;

    int i0 = base + t * 4;
    int4 v = make_int4(0, 0, 0, 0);
    if (i0 + 3 < n) v = *(const int4*)&g_cnt_in[i0];
    else {
        if (i0     < n) v.x = g_cnt_in[i0];
        if (i0 + 1 < n) v.y = g_cnt_in[i0 + 1];
        if (i0 + 2 < n) v.z = g_cnt_in[i0 + 2];
        if (i0 + 3 < n) v.w = g_cnt_in[i0 + 3];
    }
    int tsum = v.x + v.y + v.z + v.w;

    int sc = tsum;
#pragma unroll
    for (int o = 1; o < 32; o <<= 1) {
        int y = __shfl_up_sync(FULL, sc, o);
        if (lane >= o) sc += y;
    }
    if (lane == 31) warp_agg[wy] = sc;
    __syncthreads();
    if (t < 8) {
        int w = warp_agg[t];
#pragma unroll
        for (int o = 1; o < 8; o <<= 1) {
            int y = __shfl_up_sync(0xffu, w, o);
            if (t >= o) w += y;
        }
        warp_agg[t] = w;
    }
    __syncthreads();
    const int blk_total = warp_agg[7];
    const int texcl = ((wy > 0) ? warp_agg[wy - 1] : 0) + sc - tsum;

    if (t == 0) {
        if (tile == 0) {
            atomicExch(&g_desc[0], (2ULL << 32) | (unsigned)blk_total);
            sh_prefix = 0;
        } else {
            atomicExch(&g_desc[tile], (1ULL << 32) | (unsigned)blk_total);
            int pfx = 0;
            for (int k = tile - 1; k >= 0; k--) {
                unsigned long long d;
                do {
                    d = atomicAdd(&g_desc[k], 0ULL);
                    if ((d >> 32) == 0ULL) __nanosleep(40);
                } while ((d >> 32) == 0ULL);
                pfx += (int)(unsigned)d;
                if ((d >> 32) == 2ULL) break;
            }
            atomicExch(&g_desc[tile], (2ULL << 32) | (unsigned)(pfx + blk_total));
            sh_prefix = pfx;
        }
    }
    __syncthreads();

    int e0 = sh_prefix + texcl;
    int e1 = e0 + v.x, e2 = e1 + v.y, e3 = e2 + v.z;
    if (i0     < n) { g_row_ptr[i0]     = e0; g_cursor[i0]     = e0; }
    if (i0 + 1 < n) { g_row_ptr[i0 + 1] = e1; g_cursor[i0 + 1] = e1; }
    if (i0 + 2 < n) { g_row_ptr[i0 + 2] = e2; g_cursor[i0 + 2] = e2; }
    if (i0 + 3 < n) { g_row_ptr[i0 + 3] = e3; g_cursor[i0 + 3] = e3; }
    if (i0     == n - 1) g_row_ptr[n] = e1;
    if (i0 + 1 == n - 1) g_row_ptr[n] = e2;
    if (i0 + 2 == n - 1) g_row_ptr[n] = e3;
    if (i0 + 3 == n - 1) g_row_ptr[n] = e3 + v.w;
}

// ------------------------------- CSR fill ----------------------------------

__global__ void k_fill(const int* __restrict__ src, const int* __restrict__ dst,
                       int e, int n) {
    int t = blockIdx.x * blockDim.x + threadIdx.x;
    if (t >= e) return;
    int s = clampi(src[t], n);
    int d = clampi(dst[t], n);
    int pos = atomicAdd(&g_cursor[d], 1);
    g_csr[pos] = s;
}

// ---------------- fused aggregation + GEMM + q epilogue --------------------
// Block = 64 rows, 256 threads (8 warps x 8 rows). Half-warp per edge stream.
// GEMM reads smem via float4 over k: WsT transposed [col][k], Us broadcast.

__device__ __forceinline__ void acc_h(float4& a, uint2 hv) {
    float2 f0 = __half22float2(*(__half2*)&hv.x);
    float2 f1 = __half22float2(*(__half2*)&hv.y);
    a.x += f0.x; a.y += f0.y; a.z += f1.x; a.w += f1.y;
}

__global__ __launch_bounds__(256, 4)
void k_agg_gemm_q(const float* __restrict__ W1, const float* __restrict__ b1,
                  const float* __restrict__ W2, const float* __restrict__ Wr,
                  int n) {
    __shared__ float WsT[D][WPAD];       // transposed W1: WsT[col][k]
    __shared__ float Us[64][D];
    __shared__ float w2s[D], b1s[D];
    const int t = threadIdx.x;

    if (t < D) {
        float s = 0.f;
#pragma unroll
        for (int j = 0; j < D; j++) s += W2[t * D + j] * Wr[j];
        w2s[t] = s;
        b1s[t] = b1[t];
    }
#pragma unroll
    for (int i = 0; i < (D * D) / 256; i++) {
        int m = t + 256 * i;
        WsT[m & (D - 1)][m >> 6] = W1[m];      // col = m%64, k = m/64
    }

    const int row0 = blockIdx.x * 64;
    const int wy = t >> 5, lane = t & 31;
    const int half = lane >> 4, cc = lane & 15;
    const uint2* h2 = (const uint2*)g_h;       // row stride = 16 uint2 (128 B)

    for (int r = 0; r < 8; r++) {
        int row = row0 + wy * 8 + r;
        bool valid = row < n;
        int start = 0, end = 0;
        if (valid) { start = g_row_ptr[row]; end = g_row_ptr[row + 1]; }

        float4 a = make_float4(0.f, 0.f, 0.f, 0.f);
        float4 b = make_float4(0.f, 0.f, 0.f, 0.f);

        if (valid && half == 0)                     // self term (staged h)
            acc_h(a, h2[row * 16 + cc]);

        int j = start + half;                        // halves interleave edges
        for (; j + 6 < end; j += 8) {                // 4 edges/half in flight
            int s0 = g_csr[j], s1 = g_csr[j + 2], s2 = g_csr[j + 4], s3 = g_csr[j + 6];
            uint2 q0 = h2[s0 * 16 + cc];
            uint2 q1 = h2[s1 * 16 + cc];
            uint2 q2 = h2[s2 * 16 + cc];
            uint2 q3 = h2[s3 * 16 + cc];
            acc_h(a, q0); acc_h(b, q1); acc_h(a, q2); acc_h(b, q3);
        }
        for (; j < end; j += 2)
            acc_h(a, h2[g_csr[j] * 16 + cc]);

        a.x += b.x; a.y += b.y; a.z += b.z; a.w += b.w;
        a.x += __shfl_xor_sync(FULL, a.x, 16);
        a.y += __shfl_xor_sync(FULL, a.y, 16);
        a.z += __shfl_xor_sync(FULL, a.z, 16);
        a.w += __shfl_xor_sync(FULL, a.w, 16);
        if (half == 0) {
            float rin = valid ? rsqrtf(1.0f + (float)g_cnt_in[row]) : 0.f;
            a.x *= rin; a.y *= rin; a.z *= rin; a.w *= rin;
            *(float4*)&Us[wy * 8 + r][cc * 4] = a;
        }
    }
    __syncthreads();

    // GEMM: thread = 8 rows x 2 cols; k vectorized by 4 (LDS.128)
    float acc[8][2];
#pragma unroll
    for (int r = 0; r < 8; r++) { acc[r][0] = 0.f; acc[r][1] = 0.f; }
#pragma unroll
    for (int k = 0; k < D; k += 4) {
        float4 w0 = *(const float4*)&WsT[lane][k];
        float4 w1 = *(const float4*)&WsT[lane + 32][k];
#pragma unroll
        for (int r = 0; r < 8; r++) {
            float4 u = *(const float4*)&Us[wy * 8 + r][k];   // 16B broadcast
            acc[r][0] = fmaf(u.x, w0.x, acc[r][0]);
            acc[r][0] = fmaf(u.y, w0.y, acc[r][0]);
            acc[r][0] = fmaf(u.z, w0.z, acc[r][0]);
            acc[r][0] = fmaf(u.w, w0.w, acc[r][0]);
            acc[r][1] = fmaf(u.x, w1.x, acc[r][1]);
            acc[r][1] = fmaf(u.y, w1.y, acc[r][1]);
            acc[r][1] = fmaf(u.z, w1.z, acc[r][1]);
            acc[r][1] = fmaf(u.w, w1.w, acc[r][1]);
        }
    }
#pragma unroll
    for (int r = 0; r < 8; r++) {
        int row = row0 + wy * 8 + r;
        float y0 = fmaxf(acc[r][0] + b1s[lane], 0.f);
        float y1 = fmaxf(acc[r][1] + b1s[lane + 32], 0.f);
        float p = y0 * w2s[lane] + y1 * w2s[lane + 32];
#pragma unroll
        for (int o = 16; o; o >>= 1) p += __shfl_xor_sync(FULL, p, o);
        if (lane == 0 && row < n)
            g_q[row] = p * rsqrtf(1.0f + (float)g_cnt_out[row]);
    }
}

// -------------------- layer-2 gather + finalize (fused) ---------------------

__global__ void k_out(const float* __restrict__ b2, const float* __restrict__ Wr,
                      const float* __restrict__ br, float* __restrict__ out, int n) {
    __shared__ float c_sh;
    if (threadIdx.x == 0) {
        float c = 0.f;
        for (int j = 0; j < D; j++) c += b2[j] * Wr[j];
        c_sh = c + br[0];
    }
    __syncthreads();
    int node = (blockIdx.x * blockDim.x + threadIdx.x) >> 4;
    int lane = threadIdx.x & 15;
    if (node >= n) return;
    int start = g_row_ptr[node], end = g_row_ptr[node + 1];
    float s = 0.f;
    for (int j = start + lane; j < end; j += 16)
        s += g_q[g_csr[j]];
#pragma unroll
    for (int o = 8; o; o >>= 1) s += __shfl_xor_sync(FULL, s, o, 16);
    if (lane == 0) {
        float rin = rsqrtf(1.0f + (float)g_cnt_in[node]);
        out[node] = fmaf(s + g_q[node], rin, c_sh);
    }
}

// -------------------------- trailing state reset ----------------------------

__global__ void k_reset(int n, int ntiles) {
    int i = blockIdx.x * 256 + threadIdx.x;
    if (i < n) { g_cnt_out[i] = 0; g_cnt_in[i] = 0; }
    if (i < ntiles) g_desc[i] = 0ULL;
    if (i == 0) g_scan_ticket = 0u;
}

// ------------------------------- launch -------------------------------------

extern "C" void kernel_launch(void* const* d_in, const int* in_sizes, int n_in,
                              void* d_out, int out_size) {
    const float* x   = (const float*)d_in[0];
    const int*   src = (const int*)d_in[1];
    const int*   dst = (const int*)d_in[2];
    const float* W1  = (const float*)d_in[3];
    const float* b1  = (const float*)d_in[4];
    const float* W2  = (const float*)d_in[5];
    const float* b2  = (const float*)d_in[6];
    const float* Wr  = (const float*)d_in[7];
    const float* br  = (const float*)d_in[8];
    float*       out = (float*)d_out;

    const int n = in_sizes[0] / D;
    const int e = in_sizes[1];
    const int ntiles = (n + SCAN_TILE - 1) / SCAN_TILE;
    const int stage_blocks = (n * (D / 4) + 255) / 256;

    k_deg<<<(e + 255) / 256, 256>>>(src, dst, e, n);                 // 0
    k_scan_stage<<<ntiles + stage_blocks, 256>>>(x, n, ntiles);      // 1
    k_fill<<<(e + 255) / 256, 256>>>(src, dst, e, n);                // 2
    k_agg_gemm_q<<<(n + 63) / 64, 256>>>(W1, b1, W2, Wr, n);         // 3 (ncu)
    k_out<<<((n * 16) + 255) / 256, 256>>>(b2, Wr, br, out, n);      // 4
    k_reset<<<(n + 255) / 256, 256>>>(n, ntiles);                    // 5
}